// round 1
// baseline (speedup 1.0000x reference)
#include <cuda_runtime.h>
#include <math.h>

#define BATCH 256
#define SRCLEN 120
#define TGTLEN 24
#define DIN 216
#define HID 1024
#define KT 16

// Ping-pong hidden state + cell state (no runtime allocation allowed)
__device__ float g_h[2][BATCH * HID];
__device__ float g_c[BATCH * HID];

// ---------------------------------------------------------------------------
// Fused LSTM step: gates[b, g*H+j] = h@W_hh^T + x@W_ih^T + b_ih + b_hh,
// then c/h update in epilogue.
// Block tile: 32 batches x 32 j x 4 gates. Grid (32, 8). 256 threads.
// Thread (tx=j within tile, ty=batch group of 4): 16 accumulators.
// ---------------------------------------------------------------------------
__global__ __launch_bounds__(256) void lstm_step_kernel(
    const float* __restrict__ x, int x_stride,
    const float* __restrict__ h_in,
    float* __restrict__ h_out,
    float* __restrict__ c,
    const float* __restrict__ W_ih,
    const float* __restrict__ W_hh,
    const float* __restrict__ b_ih,
    const float* __restrict__ b_hh)
{
    __shared__ float Ws[KT][128];  // [k][gcol], gcol = g*32 + jj (conflict-free reads)
    __shared__ float Hs[KT][33];   // [k][b]

    const int tid = threadIdx.x;
    const int tx = tid & 31;   // j index within tile
    const int ty = tid >> 5;   // 0..7 -> batches b0 + ty*4 + 0..3
    const int j0 = blockIdx.x * 32;
    const int b0 = blockIdx.y * 32;

    float acc[4][4];
#pragma unroll
    for (int g = 0; g < 4; g++)
#pragma unroll
        for (int i = 0; i < 4; i++) acc[g][i] = 0.f;

    // phase 0: W_hh @ h_in (K=1024); phase 1: W_ih @ x (K=216)
    for (int phase = 0; phase < 2; phase++) {
        const float* Wm = phase ? W_ih : W_hh;
        const float* Xm = phase ? x : h_in;
        const int Klen = phase ? DIN : HID;
        const int wstride = Klen;               // weight row stride
        const int xstride = phase ? x_stride : HID;
        const int ntiles = (Klen + KT - 1) / KT;

        for (int kt = 0; kt < ntiles; kt++) {
            const int k0 = kt * KT;
            __syncthreads();
            // W tile: 128 rows x 16 k = 512 float4, 2 per thread (zero-pad OOB)
#pragma unroll
            for (int it = 0; it < 2; it++) {
                int m = tid + it * 256;          // 0..511
                int row = m >> 2;                // 0..127 == gcol
                int f4 = m & 3;
                int kk = f4 * 4;
                int g = row >> 5, jj = row & 31;
                int grow = g * HID + j0 + jj;
                float4 v = make_float4(0.f, 0.f, 0.f, 0.f);
                if (k0 + kk < Klen)
                    v = *reinterpret_cast<const float4*>(
                        Wm + (size_t)grow * wstride + k0 + kk);
                Ws[kk + 0][row] = v.x;
                Ws[kk + 1][row] = v.y;
                Ws[kk + 2][row] = v.z;
                Ws[kk + 3][row] = v.w;
            }
            // X tile: 32 b x 16 k = 128 float4
            if (tid < 128) {
                int bi = tid >> 2;
                int f4 = tid & 3;
                int kk = f4 * 4;
                float4 v = make_float4(0.f, 0.f, 0.f, 0.f);
                if (k0 + kk < Klen)
                    v = *reinterpret_cast<const float4*>(
                        Xm + (size_t)(b0 + bi) * xstride + k0 + kk);
                Hs[kk + 0][bi] = v.x;
                Hs[kk + 1][bi] = v.y;
                Hs[kk + 2][bi] = v.z;
                Hs[kk + 3][bi] = v.w;
            }
            __syncthreads();
            // inner product (padded tiles are zero, so no kmax guard needed)
#pragma unroll
            for (int k = 0; k < KT; k++) {
                float h0v = Hs[k][ty * 4 + 0];
                float h1v = Hs[k][ty * 4 + 1];
                float h2v = Hs[k][ty * 4 + 2];
                float h3v = Hs[k][ty * 4 + 3];
#pragma unroll
                for (int g = 0; g < 4; g++) {
                    float w = Ws[k][g * 32 + tx];
                    acc[g][0] += w * h0v;
                    acc[g][1] += w * h1v;
                    acc[g][2] += w * h2v;
                    acc[g][3] += w * h3v;
                }
            }
        }
    }

    // Epilogue: biases + LSTM cell update (PyTorch gate order i,f,g,o)
    const int j = j0 + tx;
    float bi0 = b_ih[0 * HID + j] + b_hh[0 * HID + j];
    float bf0 = b_ih[1 * HID + j] + b_hh[1 * HID + j];
    float bg0 = b_ih[2 * HID + j] + b_hh[2 * HID + j];
    float bo0 = b_ih[3 * HID + j] + b_hh[3 * HID + j];
#pragma unroll
    for (int bi = 0; bi < 4; bi++) {
        int b = b0 + ty * 4 + bi;
        float gi = acc[0][bi] + bi0;
        float gf = acc[1][bi] + bf0;
        float gg = acc[2][bi] + bg0;
        float go = acc[3][bi] + bo0;
        float iv = 1.f / (1.f + expf(-gi));
        float fv = 1.f / (1.f + expf(-gf));
        float gv = tanhf(gg);
        float ov = 1.f / (1.f + expf(-go));
        size_t idx = (size_t)b * HID + j;
        float cn = fv * c[idx] + iv * gv;
        c[idx] = cn;
        h_out[idx] = ov * tanhf(cn);
    }
}

// ---------------------------------------------------------------------------
// Output projection: out[b,d] = h[b,:] @ W_out[d,:] + b_out[d]
// Block: 16x16 threads, tile 16b x 16d, K tile 16. Grid (14, 16).
// ---------------------------------------------------------------------------
__global__ __launch_bounds__(256) void out_proj_kernel(
    const float* __restrict__ h,
    const float* __restrict__ W_out,
    const float* __restrict__ b_out,
    float* __restrict__ out, int out_stride)
{
    __shared__ float Hs[16][17];  // [k][b]
    __shared__ float Wo[16][17];  // [k][d]

    const int tid = threadIdx.x;
    const int txd = tid & 15;  // d / k loader index
    const int tyb = tid >> 4;  // b / d loader index
    const int d0 = blockIdx.x * 16;
    const int b0 = blockIdx.y * 16;

    float acc = 0.f;
    for (int k0 = 0; k0 < HID; k0 += 16) {
        __syncthreads();
        Hs[txd][tyb] = h[(size_t)(b0 + tyb) * HID + k0 + txd];
        Wo[txd][tyb] = (d0 + tyb < DIN)
            ? W_out[(size_t)(d0 + tyb) * HID + k0 + txd] : 0.f;
        __syncthreads();
#pragma unroll
        for (int k = 0; k < 16; k++)
            acc += Hs[k][tyb] * Wo[k][txd];
    }
    if (d0 + txd < DIN)
        out[(size_t)(b0 + tyb) * out_stride + d0 + txd] = acc + b_out[d0 + txd];
}

// ---------------------------------------------------------------------------
extern "C" void kernel_launch(void* const* d_in, const int* in_sizes, int n_in,
                              void* d_out, int out_size)
{
    const float* src   = (const float*)d_in[0];
    // d_in[1] = tgt (unused by the reference: decoder feeds back its own output)
    const float* W_ih  = (const float*)d_in[2];
    const float* W_hh  = (const float*)d_in[3];
    const float* b_ih  = (const float*)d_in[4];
    const float* b_hh  = (const float*)d_in[5];
    const float* W_out = (const float*)d_in[6];
    const float* b_out = (const float*)d_in[7];
    float* out = (float*)d_out;

    float* h_base = nullptr;
    float* c_ptr = nullptr;
    cudaGetSymbolAddress((void**)&h_base, g_h);
    cudaGetSymbolAddress((void**)&c_ptr, g_c);
    float* hb[2] = {h_base, h_base + BATCH * HID};

    cudaMemsetAsync(hb[0], 0, (size_t)BATCH * HID * sizeof(float));
    cudaMemsetAsync(c_ptr, 0, (size_t)BATCH * HID * sizeof(float));

    dim3 grid(32, 8);     // 1024 j / 32, 256 b / 32
    dim3 pgrid(14, 16);   // ceil(216/16), 256/16
    int cur = 0;

    // Encoder: teacher-forced over src, x_t = src[:, s, :]
    for (int s = 0; s < SRCLEN; s++) {
        lstm_step_kernel<<<grid, 256>>>(src + (size_t)s * DIN, SRCLEN * DIN,
                                        hb[cur], hb[1 - cur], c_ptr,
                                        W_ih, W_hh, b_ih, b_hh);
        cur ^= 1;
    }

    // Decoder: first x = src[:, -1, :], then fed-back projected output
    const float* x = src + (size_t)(SRCLEN - 1) * DIN;
    int xs = SRCLEN * DIN;
    for (int t = 0; t < TGTLEN; t++) {
        lstm_step_kernel<<<grid, 256>>>(x, xs, hb[cur], hb[1 - cur], c_ptr,
                                        W_ih, W_hh, b_ih, b_hh);
        cur ^= 1;
        out_proj_kernel<<<pgrid, 256>>>(hb[cur], W_out, b_out,
                                        out + (size_t)t * DIN, TGTLEN * DIN);
        x = out + (size_t)t * DIN;
        xs = TGTLEN * DIN;
    }
}

// round 3
// speedup vs baseline: 2.5951x; 2.5951x over previous
#include <cuda_runtime.h>
#include <cuda_bf16.h>
#include <cstdint>
#include <math.h>

#define BATCH 256
#define SRCLEN 120
#define TGTLEN 24
#define DIN 216
#define HID 1024
#define KPAD 256

#define KC 32                 // K per pipeline chunk
#define NCHUNK_H (HID / KC)   // 32
#define NCHUNK_X (KPAD / KC)  // 8
#define NCHUNK (NCHUNK_H + NCHUNK_X)

#define AROW 80               // smem row stride bytes (40 halfs)
#define OFF_AHI 0
#define OFF_ALO 10240
#define OFF_BHI 20480
#define OFF_BLO 25600
#define STAGE_BYTES 30720
#define SMEM_TOTAL (2 * STAGE_BYTES)

// ---------------------------------------------------------------------------
// Static device scratch (no runtime allocation allowed)
// ---------------------------------------------------------------------------
__device__ __nv_bfloat16 g_Whh_hi[4096 * HID];
__device__ __nv_bfloat16 g_Whh_lo[4096 * HID];
__device__ __nv_bfloat16 g_Wih_hi[4096 * KPAD];
__device__ __nv_bfloat16 g_Wih_lo[4096 * KPAD];
__device__ __nv_bfloat16 g_Xsrc_hi[SRCLEN * BATCH * KPAD];
__device__ __nv_bfloat16 g_Xsrc_lo[SRCLEN * BATCH * KPAD];
__device__ __nv_bfloat16 g_xdec_hi[BATCH * KPAD];
__device__ __nv_bfloat16 g_xdec_lo[BATCH * KPAD];
__device__ __nv_bfloat16 g_hhi[2][BATCH * HID];
__device__ __nv_bfloat16 g_hlo[2][BATCH * HID];
__device__ float g_hf[BATCH * HID];
__device__ float g_c[BATCH * HID];

// ---------------------------------------------------------------------------
// sm_80-safe PTX helpers
// ---------------------------------------------------------------------------
__device__ __forceinline__ uint32_t smem_u32(const void* p) {
    return (uint32_t)__cvta_generic_to_shared(p);
}
__device__ __forceinline__ void cp_async16(uint32_t saddr, const void* gaddr) {
    asm volatile("cp.async.cg.shared.global [%0], [%1], 16;" ::
                 "r"(saddr), "l"(gaddr));
}
__device__ __forceinline__ void cp_commit() {
    asm volatile("cp.async.commit_group;");
}
__device__ __forceinline__ void cp_wait1() {
    asm volatile("cp.async.wait_group 1;");
}
__device__ __forceinline__ void cp_wait0() {
    asm volatile("cp.async.wait_group 0;");
}
__device__ __forceinline__ void ldmx4(uint32_t addr, uint32_t* r) {
    asm volatile("ldmatrix.sync.aligned.m8n8.x4.shared.b16 {%0,%1,%2,%3}, [%4];"
                 : "=r"(r[0]), "=r"(r[1]), "=r"(r[2]), "=r"(r[3]) : "r"(addr));
}
__device__ __forceinline__ void mma_bf16(float* d, const uint32_t* a,
                                         uint32_t b0, uint32_t b1) {
    asm volatile(
        "mma.sync.aligned.m16n8k16.row.col.f32.bf16.bf16.f32 "
        "{%0,%1,%2,%3}, {%4,%5,%6,%7}, {%8,%9}, {%0,%1,%2,%3};"
        : "+f"(d[0]), "+f"(d[1]), "+f"(d[2]), "+f"(d[3])
        : "r"(a[0]), "r"(a[1]), "r"(a[2]), "r"(a[3]), "r"(b0), "r"(b1));
}

// ---------------------------------------------------------------------------
// Fused LSTM step via bf16-split HMMA.
// CTA tile: M=128 ({4 gates} x {32 j}), N=64 batches. Grid (32, 4), 256 thr.
// ---------------------------------------------------------------------------
__global__ __launch_bounds__(256) void lstm_mma_step(
    const __nv_bfloat16* __restrict__ x_hi, const __nv_bfloat16* __restrict__ x_lo,
    const __nv_bfloat16* __restrict__ h_hi_in, const __nv_bfloat16* __restrict__ h_lo_in,
    float* __restrict__ h_out,
    __nv_bfloat16* __restrict__ h_hi_out, __nv_bfloat16* __restrict__ h_lo_out,
    float* __restrict__ c,
    const float* __restrict__ b_ih, const float* __restrict__ b_hh)
{
    extern __shared__ __align__(128) char sm[];
    const uint32_t smb = smem_u32(sm);

    const int tid = threadIdx.x;
    const int wid = tid >> 5;
    const int lane = tid & 31;
    const int j0 = blockIdx.x * 32;
    const int b0 = blockIdx.y * 64;

    const int moff = (wid & 3) * 32;   // warp M offset (0..96)
    const int noff = (wid >> 2) * 32;  // warp N offset (0 or 32)

    float acc[2][4][4];
#pragma unroll
    for (int t = 0; t < 2; t++)
#pragma unroll
        for (int q = 0; q < 4; q++)
#pragma unroll
            for (int i = 0; i < 4; i++) acc[t][q][i] = 0.f;

    // ---------------- loader lambda (cp.async, 6 x 16B per thread) --------
    auto issue_loads = [&](int chunk, int stage) {
        const __nv_bfloat16 *Ahi, *Alo, *Bhi, *Blo;
        int ks, k0;
        if (chunk < NCHUNK_H) {
            Ahi = g_Whh_hi; Alo = g_Whh_lo; Bhi = h_hi_in; Blo = h_lo_in;
            ks = HID; k0 = chunk * KC;
        } else {
            Ahi = g_Wih_hi; Alo = g_Wih_lo; Bhi = x_hi; Blo = x_lo;
            ks = KPAD; k0 = (chunk - NCHUNK_H) * KC;
        }
        const uint32_t sbase = smb + stage * STAGE_BYTES;
#pragma unroll
        for (int i = 0; i < 6; i++) {
            int o = tid + i * 256;
            const __nv_bfloat16* g;
            uint32_t soff;
            if (o < 1024) {                       // A: 128 rows x 4 chunks, hi+lo
                int m = o & 511;
                int r = m >> 2, c4 = m & 3;
                int grow = ((r >> 5) * HID) + j0 + (r & 31);
                g = ((o < 512) ? Ahi : Alo) + (size_t)grow * ks + k0 + c4 * 8;
                soff = ((o < 512) ? OFF_AHI : OFF_ALO) + r * AROW + c4 * 16;
            } else {                              // B: 64 rows x 4 chunks, hi+lo
                int m = o - 1024;
                int mm = m & 255;
                int r = mm >> 2, c4 = mm & 3;
                g = ((m < 256) ? Bhi : Blo) + (size_t)(b0 + r) * ks + k0 + c4 * 8;
                soff = ((m < 256) ? OFF_BHI : OFF_BLO) + r * AROW + c4 * 16;
            }
            cp_async16(sbase + soff, g);
        }
        cp_commit();
    };

    // ---------------- compute lambda (2 x k16 per chunk) ------------------
    auto compute_chunk = [&](int stage) {
        const uint32_t ab = smb + stage * STAGE_BYTES;
#pragma unroll
        for (int kk = 0; kk < KC; kk += 16) {
            const int col = kk + ((lane >> 4) << 3);   // ldmatrix column (halfs)
            uint32_t a_hi[2][4], a_lo[2][4];
#pragma unroll
            for (int t = 0; t < 2; t++) {
                int row = moff + t * 16 + (lane & 15);
                ldmx4(ab + OFF_AHI + row * AROW + col * 2, a_hi[t]);
                ldmx4(ab + OFF_ALO + row * AROW + col * 2, a_lo[t]);
            }
            uint32_t b_hi[2][4], b_lo[2][4];
#pragma unroll
            for (int u = 0; u < 2; u++) {
                int row = noff + u * 16 + (lane & 15);
                ldmx4(ab + OFF_BHI + row * AROW + col * 2, b_hi[u]);
                ldmx4(ab + OFF_BLO + row * AROW + col * 2, b_lo[u]);
            }
#pragma unroll
            for (int t = 0; t < 2; t++)
#pragma unroll
                for (int q = 0; q < 4; q++) {
                    int u = q >> 1, v = q & 1;
                    mma_bf16(acc[t][q], a_hi[t], b_hi[u][v], b_hi[u][v + 2]);
                    mma_bf16(acc[t][q], a_hi[t], b_lo[u][v], b_lo[u][v + 2]);
                    mma_bf16(acc[t][q], a_lo[t], b_hi[u][v], b_hi[u][v + 2]);
                }
        }
    };

    // ---------------- pipelined mainloop ----------------------------------
    issue_loads(0, 0);
    for (int cidx = 0; cidx < NCHUNK; cidx++) {
        if (cidx + 1 < NCHUNK) {
            issue_loads(cidx + 1, (cidx + 1) & 1);
            cp_wait1();
        } else {
            cp_wait0();
        }
        __syncthreads();
        compute_chunk(cidx & 1);
        __syncthreads();
    }

    // ---------------- epilogue: frags -> smem -> LSTM pointwise -----------
    float* Dsm = reinterpret_cast<float*>(sm);    // [128][68] stride
#pragma unroll
    for (int t = 0; t < 2; t++)
#pragma unroll
        for (int q = 0; q < 4; q++) {
            int r0 = moff + t * 16 + (lane >> 2);
            int c0 = noff + q * 8 + (lane & 3) * 2;
            Dsm[r0 * 68 + c0]       = acc[t][q][0];
            Dsm[r0 * 68 + c0 + 1]   = acc[t][q][1];
            Dsm[(r0 + 8) * 68 + c0]     = acc[t][q][2];
            Dsm[(r0 + 8) * 68 + c0 + 1] = acc[t][q][3];
        }
    __syncthreads();

#pragma unroll
    for (int i = 0; i < 8; i++) {
        int id = tid + i * 256;      // 0..2047
        int bb = id >> 5;            // 0..63
        int jj = id & 31;
        int b = b0 + bb;
        int jg = j0 + jj;
        float gi = Dsm[(0   + jj) * 68 + bb] + b_ih[jg]           + b_hh[jg];
        float gf = Dsm[(32  + jj) * 68 + bb] + b_ih[HID + jg]     + b_hh[HID + jg];
        float gg = Dsm[(64  + jj) * 68 + bb] + b_ih[2*HID + jg]   + b_hh[2*HID + jg];
        float go = Dsm[(96  + jj) * 68 + bb] + b_ih[3*HID + jg]   + b_hh[3*HID + jg];
        float iv = 1.f / (1.f + expf(-gi));
        float fv = 1.f / (1.f + expf(-gf));
        float gv = tanhf(gg);
        float ov = 1.f / (1.f + expf(-go));
        size_t idx = (size_t)b * HID + jg;
        float cn = fv * c[idx] + iv * gv;
        c[idx] = cn;
        float hv = ov * tanhf(cn);
        h_out[idx] = hv;
        __nv_bfloat16 hh = __float2bfloat16(hv);
        h_hi_out[idx] = hh;
        h_lo_out[idx] = __float2bfloat16(hv - __bfloat162float(hh));
    }
}

// ---------------------------------------------------------------------------
// Conversion kernels
// ---------------------------------------------------------------------------
__global__ void split_mat_kernel(const float* __restrict__ src,
                                 __nv_bfloat16* __restrict__ hi,
                                 __nv_bfloat16* __restrict__ lo, int n) {
    int i = blockIdx.x * blockDim.x + threadIdx.x;
    if (i < n) {
        float v = src[i];
        __nv_bfloat16 h = __float2bfloat16(v);
        hi[i] = h;
        lo[i] = __float2bfloat16(v - __bfloat162float(h));
    }
}

__global__ void split_pad_kernel(const float* __restrict__ src, int srcStride, int srcK,
                                 __nv_bfloat16* __restrict__ hi,
                                 __nv_bfloat16* __restrict__ lo, int rows, int dstK) {
    int i = blockIdx.x * blockDim.x + threadIdx.x;
    if (i < rows * dstK) {
        int r = i / dstK, k = i % dstK;
        float v = (k < srcK) ? src[(size_t)r * srcStride + k] : 0.f;
        __nv_bfloat16 h = __float2bfloat16(v);
        hi[i] = h;
        lo[i] = __float2bfloat16(v - __bfloat162float(h));
    }
}

__global__ void split_src_kernel(const float* __restrict__ src,
                                 __nv_bfloat16* __restrict__ hi,
                                 __nv_bfloat16* __restrict__ lo) {
    int i = blockIdx.x * blockDim.x + threadIdx.x;
    if (i < SRCLEN * BATCH * KPAD) {
        int k = i & (KPAD - 1);
        int sb = i >> 8;
        int b = sb & (BATCH - 1);
        int s = sb >> 8;
        float v = (k < DIN) ? src[((size_t)b * SRCLEN + s) * DIN + k] : 0.f;
        __nv_bfloat16 h = __float2bfloat16(v);
        hi[i] = h;
        lo[i] = __float2bfloat16(v - __bfloat162float(h));
    }
}

// ---------------------------------------------------------------------------
// Output projection: out[b,d] = h[b,:] @ W_out[d,:] + b_out[d]
// ---------------------------------------------------------------------------
__global__ __launch_bounds__(256) void out_proj_kernel(
    const float* __restrict__ h,
    const float* __restrict__ W_out,
    const float* __restrict__ b_out,
    float* __restrict__ out, int out_stride)
{
    __shared__ float Hs[16][17];
    __shared__ float Wo[16][17];

    const int tid = threadIdx.x;
    const int txd = tid & 15;
    const int tyb = tid >> 4;
    const int d0 = blockIdx.x * 16;
    const int b0 = blockIdx.y * 16;

    float acc = 0.f;
    for (int k0 = 0; k0 < HID; k0 += 16) {
        __syncthreads();
        Hs[txd][tyb] = h[(size_t)(b0 + tyb) * HID + k0 + txd];
        Wo[txd][tyb] = (d0 + tyb < DIN)
            ? W_out[(size_t)(d0 + tyb) * HID + k0 + txd] : 0.f;
        __syncthreads();
#pragma unroll
        for (int k = 0; k < 16; k++)
            acc += Hs[k][tyb] * Wo[k][txd];
    }
    if (d0 + txd < DIN)
        out[(size_t)(b0 + tyb) * out_stride + d0 + txd] = acc + b_out[d0 + txd];
}

// ---------------------------------------------------------------------------
extern "C" void kernel_launch(void* const* d_in, const int* in_sizes, int n_in,
                              void* d_out, int out_size)
{
    const float* src   = (const float*)d_in[0];
    const float* W_ih  = (const float*)d_in[2];
    const float* W_hh  = (const float*)d_in[3];
    const float* b_ih  = (const float*)d_in[4];
    const float* b_hh  = (const float*)d_in[5];
    const float* W_out = (const float*)d_in[6];
    const float* b_out = (const float*)d_in[7];
    float* out = (float*)d_out;

    static bool attr_set = false;
    if (!attr_set) {
        cudaFuncSetAttribute(lstm_mma_step,
                             cudaFuncAttributeMaxDynamicSharedMemorySize, SMEM_TOTAL);
        attr_set = true;
    }

    __nv_bfloat16 *Whh_hi, *Wih_hi, *Xs_hi, *Xs_lo, *xd_hi, *xd_lo, *hhi, *hlo;
    __nv_bfloat16 *Whh_lo, *Wih_lo;
    float *hf, *cc;
    cudaGetSymbolAddress((void**)&Whh_hi, g_Whh_hi);
    cudaGetSymbolAddress((void**)&Whh_lo, g_Whh_lo);
    cudaGetSymbolAddress((void**)&Wih_hi, g_Wih_hi);
    cudaGetSymbolAddress((void**)&Wih_lo, g_Wih_lo);
    cudaGetSymbolAddress((void**)&Xs_hi, g_Xsrc_hi);
    cudaGetSymbolAddress((void**)&Xs_lo, g_Xsrc_lo);
    cudaGetSymbolAddress((void**)&xd_hi, g_xdec_hi);
    cudaGetSymbolAddress((void**)&xd_lo, g_xdec_lo);
    cudaGetSymbolAddress((void**)&hhi, g_hhi);
    cudaGetSymbolAddress((void**)&hlo, g_hlo);
    cudaGetSymbolAddress((void**)&hf, g_hf);
    cudaGetSymbolAddress((void**)&cc, g_c);
    __nv_bfloat16* hhb[2] = {hhi, hhi + BATCH * HID};
    __nv_bfloat16* hlb[2] = {hlo, hlo + BATCH * HID};

    cudaMemsetAsync(hhb[0], 0, (size_t)BATCH * HID * sizeof(__nv_bfloat16));
    cudaMemsetAsync(hlb[0], 0, (size_t)BATCH * HID * sizeof(__nv_bfloat16));
    cudaMemsetAsync(cc, 0, (size_t)BATCH * HID * sizeof(float));

    {
        int n = 4096 * HID;
        split_mat_kernel<<<(n + 255) / 256, 256>>>(W_hh, Whh_hi, Whh_lo, n);
        split_pad_kernel<<<(4096 * KPAD + 255) / 256, 256>>>(W_ih, DIN, DIN,
                                                             Wih_hi, Wih_lo, 4096, KPAD);
        int m = SRCLEN * BATCH * KPAD;
        split_src_kernel<<<(m + 255) / 256, 256>>>(src, Xs_hi, Xs_lo);
    }

    dim3 grid(32, 4);
    dim3 pgrid(14, 16);
    int cur = 0;

    // Encoder
    for (int s = 0; s < SRCLEN; s++) {
        lstm_mma_step<<<grid, 256, SMEM_TOTAL>>>(
            Xs_hi + (size_t)s * BATCH * KPAD, Xs_lo + (size_t)s * BATCH * KPAD,
            hhb[cur], hlb[cur], hf, hhb[1 - cur], hlb[1 - cur], cc, b_ih, b_hh);
        cur ^= 1;
    }

    // Decoder
    const __nv_bfloat16* x_hi = Xs_hi + (size_t)(SRCLEN - 1) * BATCH * KPAD;
    const __nv_bfloat16* x_lo = Xs_lo + (size_t)(SRCLEN - 1) * BATCH * KPAD;
    for (int t = 0; t < TGTLEN; t++) {
        lstm_mma_step<<<grid, 256, SMEM_TOTAL>>>(
            x_hi, x_lo, hhb[cur], hlb[cur], hf, hhb[1 - cur], hlb[1 - cur],
            cc, b_ih, b_hh);
        cur ^= 1;
        out_proj_kernel<<<pgrid, 256>>>(hf, W_out, b_out,
                                        out + (size_t)t * DIN, TGTLEN * DIN);
        if (t + 1 < TGTLEN) {
            split_pad_kernel<<<(BATCH * KPAD + 255) / 256, 256>>>(
                out + (size_t)t * DIN, TGTLEN * DIN, DIN,
                xd_hi, xd_lo, BATCH, KPAD);
            x_hi = xd_hi;
            x_lo = xd_lo;
        }
    }
}

// round 4
// speedup vs baseline: 2.6264x; 1.0120x over previous
#include <cuda_runtime.h>
#include <cuda_bf16.h>
#include <cstdint>
#include <math.h>

#define BATCH 256
#define SRCLEN 120
#define TGTLEN 24
#define DIN 216
#define HID 1024
#define KPAD 256

#define KC 32                 // K per pipeline chunk
#define NCHUNK_H (HID / KC)   // 32
#define NCHUNK_X (KPAD / KC)  // 8
#define NCHUNK (NCHUNK_H + NCHUNK_X)
#define NSTAGE 3

#define AROW 80               // smem row stride bytes (40 halfs)
#define OFF_AHI 0
#define OFF_ALO 10240
#define OFF_BHI 20480
#define OFF_BLO 25600
#define STAGE_BYTES 30720
#define SMEM_TOTAL (NSTAGE * STAGE_BYTES)

// ---------------------------------------------------------------------------
// Static device scratch (no runtime allocation allowed)
// ---------------------------------------------------------------------------
__device__ __nv_bfloat16 g_Whh_hi[4096 * HID];
__device__ __nv_bfloat16 g_Whh_lo[4096 * HID];
__device__ __nv_bfloat16 g_Wih_hi[4096 * KPAD];
__device__ __nv_bfloat16 g_Wih_lo[4096 * KPAD];
__device__ __nv_bfloat16 g_Xsrc_hi[SRCLEN * BATCH * KPAD];
__device__ __nv_bfloat16 g_Xsrc_lo[SRCLEN * BATCH * KPAD];
__device__ __nv_bfloat16 g_xdec_hi[BATCH * KPAD];
__device__ __nv_bfloat16 g_xdec_lo[BATCH * KPAD];
__device__ __nv_bfloat16 g_hhi[2][BATCH * HID];
__device__ __nv_bfloat16 g_hlo[2][BATCH * HID];
__device__ float g_hf[BATCH * HID];
__device__ float g_c[BATCH * HID];

// ---------------------------------------------------------------------------
// sm_80-safe PTX helpers
// ---------------------------------------------------------------------------
__device__ __forceinline__ uint32_t smem_u32(const void* p) {
    return (uint32_t)__cvta_generic_to_shared(p);
}
__device__ __forceinline__ void cp_async16(uint32_t saddr, const void* gaddr) {
    asm volatile("cp.async.cg.shared.global [%0], [%1], 16;" ::
                 "r"(saddr), "l"(gaddr));
}
__device__ __forceinline__ void cp_commit() {
    asm volatile("cp.async.commit_group;");
}
__device__ __forceinline__ void cp_wait2() {
    asm volatile("cp.async.wait_group 2;");
}
__device__ __forceinline__ void cp_wait1() {
    asm volatile("cp.async.wait_group 1;");
}
__device__ __forceinline__ void cp_wait0() {
    asm volatile("cp.async.wait_group 0;");
}
__device__ __forceinline__ void ldmx4(uint32_t addr, uint32_t* r) {
    asm volatile("ldmatrix.sync.aligned.m8n8.x4.shared.b16 {%0,%1,%2,%3}, [%4];"
                 : "=r"(r[0]), "=r"(r[1]), "=r"(r[2]), "=r"(r[3]) : "r"(addr));
}
__device__ __forceinline__ void mma_bf16(float* d, const uint32_t* a,
                                         uint32_t b0, uint32_t b1) {
    asm volatile(
        "mma.sync.aligned.m16n8k16.row.col.f32.bf16.bf16.f32 "
        "{%0,%1,%2,%3}, {%4,%5,%6,%7}, {%8,%9}, {%0,%1,%2,%3};"
        : "+f"(d[0]), "+f"(d[1]), "+f"(d[2]), "+f"(d[3])
        : "r"(a[0]), "r"(a[1]), "r"(a[2]), "r"(a[3]), "r"(b0), "r"(b1));
}

// ---------------------------------------------------------------------------
// Fused LSTM step via bf16-split HMMA.
// CTA tile: M=128 ({4 gates} x {32 j}), N=64 batches. Grid (32, 4), 512 thr.
// 16 warps, warp tile 32x16 (4 M-warps x 4 N-warps). 3-stage cp.async pipe.
// ---------------------------------------------------------------------------
__global__ __launch_bounds__(512) void lstm_mma_step(
    const __nv_bfloat16* __restrict__ x_hi, const __nv_bfloat16* __restrict__ x_lo,
    const __nv_bfloat16* __restrict__ h_hi_in, const __nv_bfloat16* __restrict__ h_lo_in,
    float* __restrict__ h_out,
    __nv_bfloat16* __restrict__ h_hi_out, __nv_bfloat16* __restrict__ h_lo_out,
    float* __restrict__ c,
    const float* __restrict__ b_ih, const float* __restrict__ b_hh)
{
    extern __shared__ __align__(128) char sm[];
    const uint32_t smb = smem_u32(sm);

    const int tid = threadIdx.x;
    const int wid = tid >> 5;
    const int lane = tid & 31;
    const int j0 = blockIdx.x * 32;
    const int b0 = blockIdx.y * 64;

    const int moff = (wid & 3) * 32;   // warp M offset (0..96)
    const int noff = (wid >> 2) * 16;  // warp N offset (0,16,32,48)

    float acc[2][2][4];
#pragma unroll
    for (int t = 0; t < 2; t++)
#pragma unroll
        for (int q = 0; q < 2; q++)
#pragma unroll
            for (int i = 0; i < 4; i++) acc[t][q][i] = 0.f;

    // ---------------- loader lambda (cp.async, 3 x 16B per thread) --------
    auto issue_loads = [&](int chunk, int stage) {
        const __nv_bfloat16 *Ahi, *Alo, *Bhi, *Blo;
        int ks, k0;
        if (chunk < NCHUNK_H) {
            Ahi = g_Whh_hi; Alo = g_Whh_lo; Bhi = h_hi_in; Blo = h_lo_in;
            ks = HID; k0 = chunk * KC;
        } else {
            Ahi = g_Wih_hi; Alo = g_Wih_lo; Bhi = x_hi; Blo = x_lo;
            ks = KPAD; k0 = (chunk - NCHUNK_H) * KC;
        }
        const uint32_t sbase = smb + stage * STAGE_BYTES;
#pragma unroll
        for (int i = 0; i < 3; i++) {
            int o = tid + i * 512;
            const __nv_bfloat16* g;
            uint32_t soff;
            if (o < 1024) {                       // A: 128 rows x 4 chunks, hi+lo
                int m = o & 511;
                int r = m >> 2, c4 = m & 3;
                int grow = ((r >> 5) * HID) + j0 + (r & 31);
                g = ((o < 512) ? Ahi : Alo) + (size_t)grow * ks + k0 + c4 * 8;
                soff = ((o < 512) ? OFF_AHI : OFF_ALO) + r * AROW + c4 * 16;
            } else {                              // B: 64 rows x 4 chunks, hi+lo
                int m = o - 1024;
                int mm = m & 255;
                int r = mm >> 2, c4 = mm & 3;
                g = ((m < 256) ? Bhi : Blo) + (size_t)(b0 + r) * ks + k0 + c4 * 8;
                soff = ((m < 256) ? OFF_BHI : OFF_BLO) + r * AROW + c4 * 16;
            }
            cp_async16(sbase + soff, g);
        }
        cp_commit();
    };

    // ---------------- compute lambda (2 x k16 per chunk) ------------------
    auto compute_chunk = [&](int stage) {
        const uint32_t ab = smb + stage * STAGE_BYTES;
#pragma unroll
        for (int kk = 0; kk < KC; kk += 16) {
            const int col = kk + ((lane >> 4) << 3);   // ldmatrix column (halfs)
            uint32_t a_hi[2][4], a_lo[2][4];
#pragma unroll
            for (int t = 0; t < 2; t++) {
                int row = moff + t * 16 + (lane & 15);
                ldmx4(ab + OFF_AHI + row * AROW + col * 2, a_hi[t]);
                ldmx4(ab + OFF_ALO + row * AROW + col * 2, a_lo[t]);
            }
            uint32_t b_hi[4], b_lo[4];
            {
                int row = noff + (lane & 15);
                ldmx4(ab + OFF_BHI + row * AROW + col * 2, b_hi);
                ldmx4(ab + OFF_BLO + row * AROW + col * 2, b_lo);
            }
#pragma unroll
            for (int t = 0; t < 2; t++)
#pragma unroll
                for (int q = 0; q < 2; q++) {
                    mma_bf16(acc[t][q], a_hi[t], b_hi[q], b_hi[q + 2]);
                    mma_bf16(acc[t][q], a_hi[t], b_lo[q], b_lo[q + 2]);
                    mma_bf16(acc[t][q], a_lo[t], b_hi[q], b_hi[q + 2]);
                }
        }
    };

    // ---------------- 3-stage pipelined mainloop --------------------------
    issue_loads(0, 0);
    issue_loads(1, 1);
    for (int cidx = 0; cidx < NCHUNK; cidx++) {
        if (cidx + 2 < NCHUNK) {
            issue_loads(cidx + 2, (cidx + 2) % NSTAGE);
            cp_wait2();
        } else if (cidx + 1 < NCHUNK) {
            cp_wait1();
        } else {
            cp_wait0();
        }
        __syncthreads();
        compute_chunk(cidx % NSTAGE);
        __syncthreads();
    }

    // ---------------- epilogue: frags -> smem -> LSTM pointwise -----------
    float* Dsm = reinterpret_cast<float*>(sm);    // [128][68] stride
#pragma unroll
    for (int t = 0; t < 2; t++)
#pragma unroll
        for (int q = 0; q < 2; q++) {
            int r0 = moff + t * 16 + (lane >> 2);
            int c0 = noff + q * 8 + (lane & 3) * 2;
            Dsm[r0 * 68 + c0]           = acc[t][q][0];
            Dsm[r0 * 68 + c0 + 1]       = acc[t][q][1];
            Dsm[(r0 + 8) * 68 + c0]     = acc[t][q][2];
            Dsm[(r0 + 8) * 68 + c0 + 1] = acc[t][q][3];
        }
    __syncthreads();

#pragma unroll
    for (int i = 0; i < 4; i++) {
        int id = tid + i * 512;      // 0..2047
        int bb = id >> 5;            // 0..63
        int jj = id & 31;
        int b = b0 + bb;
        int jg = j0 + jj;
        float gi = Dsm[(0   + jj) * 68 + bb] + b_ih[jg]           + b_hh[jg];
        float gf = Dsm[(32  + jj) * 68 + bb] + b_ih[HID + jg]     + b_hh[HID + jg];
        float gg = Dsm[(64  + jj) * 68 + bb] + b_ih[2*HID + jg]   + b_hh[2*HID + jg];
        float go = Dsm[(96  + jj) * 68 + bb] + b_ih[3*HID + jg]   + b_hh[3*HID + jg];
        float iv = 1.f / (1.f + expf(-gi));
        float fv = 1.f / (1.f + expf(-gf));
        float gv = tanhf(gg);
        float ov = 1.f / (1.f + expf(-go));
        size_t idx = (size_t)b * HID + jg;
        float cn = fv * c[idx] + iv * gv;
        c[idx] = cn;
        float hv = ov * tanhf(cn);
        h_out[idx] = hv;
        __nv_bfloat16 hh = __float2bfloat16(hv);
        h_hi_out[idx] = hh;
        h_lo_out[idx] = __float2bfloat16(hv - __bfloat162float(hh));
    }
}

// ---------------------------------------------------------------------------
// Conversion kernels
// ---------------------------------------------------------------------------
__global__ void split_mat_kernel(const float* __restrict__ src,
                                 __nv_bfloat16* __restrict__ hi,
                                 __nv_bfloat16* __restrict__ lo, int n) {
    int i = blockIdx.x * blockDim.x + threadIdx.x;
    if (i < n) {
        float v = src[i];
        __nv_bfloat16 h = __float2bfloat16(v);
        hi[i] = h;
        lo[i] = __float2bfloat16(v - __bfloat162float(h));
    }
}

__global__ void split_pad_kernel(const float* __restrict__ src, int srcStride, int srcK,
                                 __nv_bfloat16* __restrict__ hi,
                                 __nv_bfloat16* __restrict__ lo, int rows, int dstK) {
    int i = blockIdx.x * blockDim.x + threadIdx.x;
    if (i < rows * dstK) {
        int r = i / dstK, k = i % dstK;
        float v = (k < srcK) ? src[(size_t)r * srcStride + k] : 0.f;
        __nv_bfloat16 h = __float2bfloat16(v);
        hi[i] = h;
        lo[i] = __float2bfloat16(v - __bfloat162float(h));
    }
}

__global__ void split_src_kernel(const float* __restrict__ src,
                                 __nv_bfloat16* __restrict__ hi,
                                 __nv_bfloat16* __restrict__ lo) {
    int i = blockIdx.x * blockDim.x + threadIdx.x;
    if (i < SRCLEN * BATCH * KPAD) {
        int k = i & (KPAD - 1);
        int sb = i >> 8;
        int b = sb & (BATCH - 1);
        int s = sb >> 8;
        float v = (k < DIN) ? src[((size_t)b * SRCLEN + s) * DIN + k] : 0.f;
        __nv_bfloat16 h = __float2bfloat16(v);
        hi[i] = h;
        lo[i] = __float2bfloat16(v - __bfloat162float(h));
    }
}

// ---------------------------------------------------------------------------
// Output projection: out[b,d] = h[b,:] @ W_out[d,:] + b_out[d]
// ---------------------------------------------------------------------------
__global__ __launch_bounds__(256) void out_proj_kernel(
    const float* __restrict__ h,
    const float* __restrict__ W_out,
    const float* __restrict__ b_out,
    float* __restrict__ out, int out_stride)
{
    __shared__ float Hs[16][17];
    __shared__ float Wo[16][17];

    const int tid = threadIdx.x;
    const int txd = tid & 15;
    const int tyb = tid >> 4;
    const int d0 = blockIdx.x * 16;
    const int b0 = blockIdx.y * 16;

    float acc = 0.f;
    for (int k0 = 0; k0 < HID; k0 += 16) {
        __syncthreads();
        Hs[txd][tyb] = h[(size_t)(b0 + tyb) * HID + k0 + txd];
        Wo[txd][tyb] = (d0 + tyb < DIN)
            ? W_out[(size_t)(d0 + tyb) * HID + k0 + txd] : 0.f;
        __syncthreads();
#pragma unroll
        for (int k = 0; k < 16; k++)
            acc += Hs[k][tyb] * Wo[k][txd];
    }
    if (d0 + txd < DIN)
        out[(size_t)(b0 + tyb) * out_stride + d0 + txd] = acc + b_out[d0 + txd];
}

// ---------------------------------------------------------------------------
extern "C" void kernel_launch(void* const* d_in, const int* in_sizes, int n_in,
                              void* d_out, int out_size)
{
    const float* src   = (const float*)d_in[0];
    const float* W_ih  = (const float*)d_in[2];
    const float* W_hh  = (const float*)d_in[3];
    const float* b_ih  = (const float*)d_in[4];
    const float* b_hh  = (const float*)d_in[5];
    const float* W_out = (const float*)d_in[6];
    const float* b_out = (const float*)d_in[7];
    float* out = (float*)d_out;

    static bool attr_set = false;
    if (!attr_set) {
        cudaFuncSetAttribute(lstm_mma_step,
                             cudaFuncAttributeMaxDynamicSharedMemorySize, SMEM_TOTAL);
        attr_set = true;
    }

    __nv_bfloat16 *Whh_hi, *Wih_hi, *Xs_hi, *Xs_lo, *xd_hi, *xd_lo, *hhi, *hlo;
    __nv_bfloat16 *Whh_lo, *Wih_lo;
    float *hf, *cc;
    cudaGetSymbolAddress((void**)&Whh_hi, g_Whh_hi);
    cudaGetSymbolAddress((void**)&Whh_lo, g_Whh_lo);
    cudaGetSymbolAddress((void**)&Wih_hi, g_Wih_hi);
    cudaGetSymbolAddress((void**)&Wih_lo, g_Wih_lo);
    cudaGetSymbolAddress((void**)&Xs_hi, g_Xsrc_hi);
    cudaGetSymbolAddress((void**)&Xs_lo, g_Xsrc_lo);
    cudaGetSymbolAddress((void**)&xd_hi, g_xdec_hi);
    cudaGetSymbolAddress((void**)&xd_lo, g_xdec_lo);
    cudaGetSymbolAddress((void**)&hhi, g_hhi);
    cudaGetSymbolAddress((void**)&hlo, g_hlo);
    cudaGetSymbolAddress((void**)&hf, g_hf);
    cudaGetSymbolAddress((void**)&cc, g_c);
    __nv_bfloat16* hhb[2] = {hhi, hhi + BATCH * HID};
    __nv_bfloat16* hlb[2] = {hlo, hlo + BATCH * HID};

    cudaMemsetAsync(hhb[0], 0, (size_t)BATCH * HID * sizeof(__nv_bfloat16));
    cudaMemsetAsync(hlb[0], 0, (size_t)BATCH * HID * sizeof(__nv_bfloat16));
    cudaMemsetAsync(cc, 0, (size_t)BATCH * HID * sizeof(float));

    {
        int n = 4096 * HID;
        split_mat_kernel<<<(n + 255) / 256, 256>>>(W_hh, Whh_hi, Whh_lo, n);
        split_pad_kernel<<<(4096 * KPAD + 255) / 256, 256>>>(W_ih, DIN, DIN,
                                                             Wih_hi, Wih_lo, 4096, KPAD);
        int m = SRCLEN * BATCH * KPAD;
        split_src_kernel<<<(m + 255) / 256, 256>>>(src, Xs_hi, Xs_lo);
    }

    dim3 grid(32, 4);
    dim3 pgrid(14, 16);
    int cur = 0;

    // Encoder
    for (int s = 0; s < SRCLEN; s++) {
        lstm_mma_step<<<grid, 512, SMEM_TOTAL>>>(
            Xs_hi + (size_t)s * BATCH * KPAD, Xs_lo + (size_t)s * BATCH * KPAD,
            hhb[cur], hlb[cur], hf, hhb[1 - cur], hlb[1 - cur], cc, b_ih, b_hh);
        cur ^= 1;
    }

    // Decoder
    const __nv_bfloat16* x_hi = Xs_hi + (size_t)(SRCLEN - 1) * BATCH * KPAD;
    const __nv_bfloat16* x_lo = Xs_lo + (size_t)(SRCLEN - 1) * BATCH * KPAD;
    for (int t = 0; t < TGTLEN; t++) {
        lstm_mma_step<<<grid, 512, SMEM_TOTAL>>>(
            x_hi, x_lo, hhb[cur], hlb[cur], hf, hhb[1 - cur], hlb[1 - cur],
            cc, b_ih, b_hh);
        cur ^= 1;
        out_proj_kernel<<<pgrid, 256>>>(hf, W_out, b_out,
                                        out + (size_t)t * DIN, TGTLEN * DIN);
        if (t + 1 < TGTLEN) {
            split_pad_kernel<<<(BATCH * KPAD + 255) / 256, 256>>>(
                out + (size_t)t * DIN, TGTLEN * DIN, DIN,
                xd_hi, xd_lo, BATCH, KPAD);
            x_hi = xd_hi;
            x_lo = xd_lo;
        }
    }
}

// round 5
// speedup vs baseline: 3.1049x; 1.1822x over previous
#include <cuda_runtime.h>
#include <cuda_bf16.h>
#include <cstdint>
#include <math.h>

#define BATCH 256
#define SRCLEN 120
#define TGTLEN 24
#define DIN 216
#define HID 1024
#define KPAD 256

#define KC 64                 // K per pipeline chunk
#define NCHUNK_H (HID / KC)   // 16
#define NCHUNK_X (KPAD / KC)  // 4
#define NCHUNK (NCHUNK_H + NCHUNK_X)
#define NSTAGE 3

#define AROW 144              // smem row stride bytes (72 halfs: 128B data + 16B pad)
#define OFF_AHI 0
#define OFF_ALO 18432
#define OFF_BHI 36864
#define OFF_BLO 46080
#define STAGE_BYTES 55296
#define SMEM_TOTAL (NSTAGE * STAGE_BYTES)

// ---------------------------------------------------------------------------
// Static device scratch (no runtime allocation allowed)
// ---------------------------------------------------------------------------
__device__ __nv_bfloat16 g_Whh_hi[4096 * HID];
__device__ __nv_bfloat16 g_Whh_lo[4096 * HID];
__device__ __nv_bfloat16 g_Wih_hi[4096 * KPAD];
__device__ __nv_bfloat16 g_Wih_lo[4096 * KPAD];
__device__ __nv_bfloat16 g_Xsrc_hi[SRCLEN * BATCH * KPAD];
__device__ __nv_bfloat16 g_Xsrc_lo[SRCLEN * BATCH * KPAD];
__device__ __nv_bfloat16 g_xdec_hi[BATCH * KPAD];
__device__ __nv_bfloat16 g_xdec_lo[BATCH * KPAD];
__device__ __nv_bfloat16 g_hhi[2][BATCH * HID];
__device__ __nv_bfloat16 g_hlo[2][BATCH * HID];
__device__ float g_hf[BATCH * HID];
__device__ float g_c[BATCH * HID];

// ---------------------------------------------------------------------------
// sm_80-safe PTX helpers
// ---------------------------------------------------------------------------
__device__ __forceinline__ uint32_t smem_u32(const void* p) {
    return (uint32_t)__cvta_generic_to_shared(p);
}
__device__ __forceinline__ void cp_async16(uint32_t saddr, const void* gaddr) {
    asm volatile("cp.async.cg.shared.global [%0], [%1], 16;" ::
                 "r"(saddr), "l"(gaddr));
}
__device__ __forceinline__ void cp_commit() {
    asm volatile("cp.async.commit_group;");
}
__device__ __forceinline__ void cp_wait1() {
    asm volatile("cp.async.wait_group 1;");
}
__device__ __forceinline__ void cp_wait0() {
    asm volatile("cp.async.wait_group 0;");
}
__device__ __forceinline__ void ldmx4(uint32_t addr, uint32_t* r) {
    asm volatile("ldmatrix.sync.aligned.m8n8.x4.shared.b16 {%0,%1,%2,%3}, [%4];"
                 : "=r"(r[0]), "=r"(r[1]), "=r"(r[2]), "=r"(r[3]) : "r"(addr));
}
__device__ __forceinline__ void mma_bf16(float* d, const uint32_t* a,
                                         uint32_t b0, uint32_t b1) {
    asm volatile(
        "mma.sync.aligned.m16n8k16.row.col.f32.bf16.bf16.f32 "
        "{%0,%1,%2,%3}, {%4,%5,%6,%7}, {%8,%9}, {%0,%1,%2,%3};"
        : "+f"(d[0]), "+f"(d[1]), "+f"(d[2]), "+f"(d[3])
        : "r"(a[0]), "r"(a[1]), "r"(a[2]), "r"(a[3]), "r"(b0), "r"(b1));
}

// ---------------------------------------------------------------------------
// Fused LSTM step via bf16-split HMMA.
// CTA tile: M=128 ({4 gates} x {32 j}), N=64 batches. Grid (32, 4), 512 thr.
// 16 warps, warp tile 32x16. KC=64 chunks, 3-stage pipe, 1 barrier/chunk.
// ---------------------------------------------------------------------------
__global__ __launch_bounds__(512) void lstm_mma_step(
    const __nv_bfloat16* __restrict__ x_hi, const __nv_bfloat16* __restrict__ x_lo,
    const __nv_bfloat16* __restrict__ h_hi_in, const __nv_bfloat16* __restrict__ h_lo_in,
    float* __restrict__ h_out,
    __nv_bfloat16* __restrict__ h_hi_out, __nv_bfloat16* __restrict__ h_lo_out,
    float* __restrict__ c,
    const float* __restrict__ b_ih, const float* __restrict__ b_hh)
{
    extern __shared__ __align__(128) char sm[];
    const uint32_t smb = smem_u32(sm);

    const int tid = threadIdx.x;
    const int wid = tid >> 5;
    const int lane = tid & 31;
    const int j0 = blockIdx.x * 32;
    const int b0 = blockIdx.y * 64;

    const int moff = (wid & 3) * 32;   // warp M offset (0..96)
    const int noff = (wid >> 2) * 16;  // warp N offset (0,16,32,48)

    float acc[2][2][4];
#pragma unroll
    for (int t = 0; t < 2; t++)
#pragma unroll
        for (int q = 0; q < 2; q++)
#pragma unroll
            for (int i = 0; i < 4; i++) acc[t][q][i] = 0.f;

    // ---------------- loader (cp.async, 6 x 16B per thread) ---------------
    auto issue_loads = [&](int chunk, int stage) {
        const __nv_bfloat16 *Ahi, *Alo, *Bhi, *Blo;
        int ks, k0;
        if (chunk < NCHUNK_H) {
            Ahi = g_Whh_hi; Alo = g_Whh_lo; Bhi = h_hi_in; Blo = h_lo_in;
            ks = HID; k0 = chunk * KC;
        } else {
            Ahi = g_Wih_hi; Alo = g_Wih_lo; Bhi = x_hi; Blo = x_lo;
            ks = KPAD; k0 = (chunk - NCHUNK_H) * KC;
        }
        const uint32_t sbase = smb + stage * STAGE_BYTES;
#pragma unroll
        for (int i = 0; i < 6; i++) {
            int o = tid + i * 512;                // 0..3071
            const __nv_bfloat16* g;
            uint32_t soff;
            if (o < 2048) {                       // A: 128 rows x 8 chunks, hi+lo
                int m = o & 1023;
                int r = m >> 3, c8 = m & 7;
                int grow = ((r >> 5) * HID) + j0 + (r & 31);
                g = ((o < 1024) ? Ahi : Alo) + (size_t)grow * ks + k0 + c8 * 8;
                soff = ((o < 1024) ? OFF_AHI : OFF_ALO) + r * AROW + c8 * 16;
            } else {                              // B: 64 rows x 8 chunks, hi+lo
                int m = o - 2048;
                int mm = m & 511;
                int r = mm >> 3, c8 = mm & 7;
                g = ((m < 512) ? Bhi : Blo) + (size_t)(b0 + r) * ks + k0 + c8 * 8;
                soff = ((m < 512) ? OFF_BHI : OFF_BLO) + r * AROW + c8 * 16;
            }
            cp_async16(sbase + soff, g);
        }
        cp_commit();
    };

    // ---------------- compute (4 x k16 per chunk) -------------------------
    auto compute_chunk = [&](int stage) {
        const uint32_t ab = smb + stage * STAGE_BYTES;
#pragma unroll
        for (int kk = 0; kk < KC; kk += 16) {
            const int col = kk + ((lane >> 4) << 3);   // ldmatrix column (halfs)
            uint32_t a_hi[2][4], a_lo[2][4];
#pragma unroll
            for (int t = 0; t < 2; t++) {
                int row = moff + t * 16 + (lane & 15);
                ldmx4(ab + OFF_AHI + row * AROW + col * 2, a_hi[t]);
                ldmx4(ab + OFF_ALO + row * AROW + col * 2, a_lo[t]);
            }
            uint32_t b_hi[4], b_lo[4];
            {
                int row = noff + (lane & 15);
                ldmx4(ab + OFF_BHI + row * AROW + col * 2, b_hi);
                ldmx4(ab + OFF_BLO + row * AROW + col * 2, b_lo);
            }
#pragma unroll
            for (int t = 0; t < 2; t++)
#pragma unroll
                for (int q = 0; q < 2; q++) {
                    mma_bf16(acc[t][q], a_hi[t], b_hi[q], b_hi[q + 2]);
                    mma_bf16(acc[t][q], a_hi[t], b_lo[q], b_lo[q + 2]);
                    mma_bf16(acc[t][q], a_lo[t], b_hi[q], b_hi[q + 2]);
                }
        }
    };

    // ---------------- pipelined mainloop: ONE barrier per chunk -----------
    // iter i: wait chunk i ready -> barrier (also licenses overwriting
    // stage (i-1)%3, consumed at iter i-1) -> prefetch chunk i+2 -> compute i
    issue_loads(0, 0);
    issue_loads(1, 1);
    for (int i = 0; i < NCHUNK; i++) {
        if (i + 1 < NCHUNK) cp_wait1(); else cp_wait0();
        __syncthreads();
        if (i + 2 < NCHUNK) issue_loads(i + 2, (i + 2) % NSTAGE);
        compute_chunk(i % NSTAGE);
    }

    // ---------------- epilogue: frags -> smem -> LSTM pointwise -----------
    // Dsm occupies stage-0 region; safe: last compute reads stage 19%3=1,
    // and the iter-19 barrier guaranteed stage 0 (chunk 18) reads finished.
    float* Dsm = reinterpret_cast<float*>(sm);    // [128][68] stride
#pragma unroll
    for (int t = 0; t < 2; t++)
#pragma unroll
        for (int q = 0; q < 2; q++) {
            int r0 = moff + t * 16 + (lane >> 2);
            int c0 = noff + q * 8 + (lane & 3) * 2;
            Dsm[r0 * 68 + c0]           = acc[t][q][0];
            Dsm[r0 * 68 + c0 + 1]       = acc[t][q][1];
            Dsm[(r0 + 8) * 68 + c0]     = acc[t][q][2];
            Dsm[(r0 + 8) * 68 + c0 + 1] = acc[t][q][3];
        }
    __syncthreads();

#pragma unroll
    for (int i = 0; i < 4; i++) {
        int id = tid + i * 512;      // 0..2047
        int bb = id >> 5;            // 0..63
        int jj = id & 31;
        int b = b0 + bb;
        int jg = j0 + jj;
        float gi = Dsm[(0   + jj) * 68 + bb] + b_ih[jg]           + b_hh[jg];
        float gf = Dsm[(32  + jj) * 68 + bb] + b_ih[HID + jg]     + b_hh[HID + jg];
        float gg = Dsm[(64  + jj) * 68 + bb] + b_ih[2*HID + jg]   + b_hh[2*HID + jg];
        float go = Dsm[(96  + jj) * 68 + bb] + b_ih[3*HID + jg]   + b_hh[3*HID + jg];
        float iv = 1.f / (1.f + expf(-gi));
        float fv = 1.f / (1.f + expf(-gf));
        float gv = tanhf(gg);
        float ov = 1.f / (1.f + expf(-go));
        size_t idx = (size_t)b * HID + jg;
        float cn = fv * c[idx] + iv * gv;
        c[idx] = cn;
        float hv = ov * tanhf(cn);
        h_out[idx] = hv;
        __nv_bfloat16 hh = __float2bfloat16(hv);
        h_hi_out[idx] = hh;
        h_lo_out[idx] = __float2bfloat16(hv - __bfloat162float(hh));
    }
}

// ---------------------------------------------------------------------------
// Conversion kernels
// ---------------------------------------------------------------------------
__global__ void split_mat_kernel(const float* __restrict__ src,
                                 __nv_bfloat16* __restrict__ hi,
                                 __nv_bfloat16* __restrict__ lo, int n) {
    int i = blockIdx.x * blockDim.x + threadIdx.x;
    if (i < n) {
        float v = src[i];
        __nv_bfloat16 h = __float2bfloat16(v);
        hi[i] = h;
        lo[i] = __float2bfloat16(v - __bfloat162float(h));
    }
}

__global__ void split_pad_kernel(const float* __restrict__ src, int srcStride, int srcK,
                                 __nv_bfloat16* __restrict__ hi,
                                 __nv_bfloat16* __restrict__ lo, int rows, int dstK) {
    int i = blockIdx.x * blockDim.x + threadIdx.x;
    if (i < rows * dstK) {
        int r = i / dstK, k = i % dstK;
        float v = (k < srcK) ? src[(size_t)r * srcStride + k] : 0.f;
        __nv_bfloat16 h = __float2bfloat16(v);
        hi[i] = h;
        lo[i] = __float2bfloat16(v - __bfloat162float(h));
    }
}

__global__ void split_src_kernel(const float* __restrict__ src,
                                 __nv_bfloat16* __restrict__ hi,
                                 __nv_bfloat16* __restrict__ lo) {
    int i = blockIdx.x * blockDim.x + threadIdx.x;
    if (i < SRCLEN * BATCH * KPAD) {
        int k = i & (KPAD - 1);
        int sb = i >> 8;
        int b = sb & (BATCH - 1);
        int s = sb >> 8;
        float v = (k < DIN) ? src[((size_t)b * SRCLEN + s) * DIN + k] : 0.f;
        __nv_bfloat16 h = __float2bfloat16(v);
        hi[i] = h;
        lo[i] = __float2bfloat16(v - __bfloat162float(h));
    }
}

// ---------------------------------------------------------------------------
// Output projection fused with feedback split:
// out[b,d] = h[b,:] @ W_out[d,:] + b_out[d]; also writes xd hi/lo (d < DIN).
// ---------------------------------------------------------------------------
__global__ __launch_bounds__(256) void out_proj_kernel(
    const float* __restrict__ h,
    const float* __restrict__ W_out,
    const float* __restrict__ b_out,
    float* __restrict__ out, int out_stride,
    __nv_bfloat16* __restrict__ xd_hi, __nv_bfloat16* __restrict__ xd_lo)
{
    __shared__ float Hs[16][17];
    __shared__ float Wo[16][17];

    const int tid = threadIdx.x;
    const int txd = tid & 15;
    const int tyb = tid >> 4;
    const int d0 = blockIdx.x * 16;
    const int b0 = blockIdx.y * 16;

    float acc = 0.f;
    for (int k0 = 0; k0 < HID; k0 += 16) {
        __syncthreads();
        Hs[txd][tyb] = h[(size_t)(b0 + tyb) * HID + k0 + txd];
        Wo[txd][tyb] = (d0 + tyb < DIN)
            ? W_out[(size_t)(d0 + tyb) * HID + k0 + txd] : 0.f;
        __syncthreads();
#pragma unroll
        for (int k = 0; k < 16; k++)
            acc += Hs[k][tyb] * Wo[k][txd];
    }
    if (d0 + txd < DIN) {
        float v = acc + b_out[d0 + txd];
        out[(size_t)(b0 + tyb) * out_stride + d0 + txd] = v;
        if (xd_hi) {
            size_t xi = (size_t)(b0 + tyb) * KPAD + d0 + txd;
            __nv_bfloat16 hh = __float2bfloat16(v);
            xd_hi[xi] = hh;
            xd_lo[xi] = __float2bfloat16(v - __bfloat162float(hh));
        }
    }
}

// ---------------------------------------------------------------------------
extern "C" void kernel_launch(void* const* d_in, const int* in_sizes, int n_in,
                              void* d_out, int out_size)
{
    const float* src   = (const float*)d_in[0];
    const float* W_ih  = (const float*)d_in[2];
    const float* W_hh  = (const float*)d_in[3];
    const float* b_ih  = (const float*)d_in[4];
    const float* b_hh  = (const float*)d_in[5];
    const float* W_out = (const float*)d_in[6];
    const float* b_out = (const float*)d_in[7];
    float* out = (float*)d_out;

    static bool attr_set = false;
    if (!attr_set) {
        cudaFuncSetAttribute(lstm_mma_step,
                             cudaFuncAttributeMaxDynamicSharedMemorySize, SMEM_TOTAL);
        attr_set = true;
    }

    __nv_bfloat16 *Whh_hi, *Wih_hi, *Xs_hi, *Xs_lo, *xd_hi, *xd_lo, *hhi, *hlo;
    __nv_bfloat16 *Whh_lo, *Wih_lo;
    float *hf, *cc;
    cudaGetSymbolAddress((void**)&Whh_hi, g_Whh_hi);
    cudaGetSymbolAddress((void**)&Whh_lo, g_Whh_lo);
    cudaGetSymbolAddress((void**)&Wih_hi, g_Wih_hi);
    cudaGetSymbolAddress((void**)&Wih_lo, g_Wih_lo);
    cudaGetSymbolAddress((void**)&Xs_hi, g_Xsrc_hi);
    cudaGetSymbolAddress((void**)&Xs_lo, g_Xsrc_lo);
    cudaGetSymbolAddress((void**)&xd_hi, g_xdec_hi);
    cudaGetSymbolAddress((void**)&xd_lo, g_xdec_lo);
    cudaGetSymbolAddress((void**)&hhi, g_hhi);
    cudaGetSymbolAddress((void**)&hlo, g_hlo);
    cudaGetSymbolAddress((void**)&hf, g_hf);
    cudaGetSymbolAddress((void**)&cc, g_c);
    __nv_bfloat16* hhb[2] = {hhi, hhi + BATCH * HID};
    __nv_bfloat16* hlb[2] = {hlo, hlo + BATCH * HID};

    cudaMemsetAsync(hhb[0], 0, (size_t)BATCH * HID * sizeof(__nv_bfloat16));
    cudaMemsetAsync(hlb[0], 0, (size_t)BATCH * HID * sizeof(__nv_bfloat16));
    cudaMemsetAsync(cc, 0, (size_t)BATCH * HID * sizeof(float));
    // zero pad zone of decoder feedback split (cols DIN..KPAD stay zero)
    cudaMemsetAsync(xd_hi, 0, (size_t)BATCH * KPAD * sizeof(__nv_bfloat16));
    cudaMemsetAsync(xd_lo, 0, (size_t)BATCH * KPAD * sizeof(__nv_bfloat16));

    {
        int n = 4096 * HID;
        split_mat_kernel<<<(n + 255) / 256, 256>>>(W_hh, Whh_hi, Whh_lo, n);
        split_pad_kernel<<<(4096 * KPAD + 255) / 256, 256>>>(W_ih, DIN, DIN,
                                                             Wih_hi, Wih_lo, 4096, KPAD);
        int m = SRCLEN * BATCH * KPAD;
        split_src_kernel<<<(m + 255) / 256, 256>>>(src, Xs_hi, Xs_lo);
    }

    dim3 grid(32, 4);
    dim3 pgrid(14, 16);
    int cur = 0;

    // Encoder
    for (int s = 0; s < SRCLEN; s++) {
        lstm_mma_step<<<grid, 512, SMEM_TOTAL>>>(
            Xs_hi + (size_t)s * BATCH * KPAD, Xs_lo + (size_t)s * BATCH * KPAD,
            hhb[cur], hlb[cur], hf, hhb[1 - cur], hlb[1 - cur], cc, b_ih, b_hh);
        cur ^= 1;
    }

    // Decoder
    const __nv_bfloat16* x_hi = Xs_hi + (size_t)(SRCLEN - 1) * BATCH * KPAD;
    const __nv_bfloat16* x_lo = Xs_lo + (size_t)(SRCLEN - 1) * BATCH * KPAD;
    for (int t = 0; t < TGTLEN; t++) {
        lstm_mma_step<<<grid, 512, SMEM_TOTAL>>>(
            x_hi, x_lo, hhb[cur], hlb[cur], hf, hhb[1 - cur], hlb[1 - cur],
            cc, b_ih, b_hh);
        cur ^= 1;
        bool feed = (t + 1 < TGTLEN);
        out_proj_kernel<<<pgrid, 256>>>(hf, W_out, b_out,
                                        out + (size_t)t * DIN, TGTLEN * DIN,
                                        feed ? xd_hi : nullptr,
                                        feed ? xd_lo : nullptr);
        x_hi = xd_hi;
        x_lo = xd_lo;
    }
}